// round 1
// baseline (speedup 1.0000x reference)
#include <cuda_runtime.h>

// Problem constants
#define TT   4096      // sequence length T
#define TM1  4095      // T-1 steps
#define EE   512       // embedding dim E
#define HH   1024      // hidden dim H
#define G4   4096      // 4*H
#define CC   1221      // output classes C
#define NCTA 128       // persistent CTAs for the recurrence

typedef unsigned long long u64;

// ---------------- scratch (static device globals; no allocation allowed) ----
__device__ float    g_emb[(size_t)TT * EE];        // gathered embeddings  (8 MB)
__device__ float    g_bias4h[G4];                  // b_ih + b_hh + last@W_ih[:,E:]
__device__ float    g_xg[(size_t)TM1 * G4];        // precomputed input gates (67 MB)
__device__ float    g_hs[(size_t)TM1 * HH];        // all hidden states (16.8 MB)
__device__ unsigned g_counter;                     // barrier counter

// ---------------- helpers ---------------------------------------------------
__device__ __forceinline__ u64 fma2(u64 a, u64 b, u64 c) {
    u64 d;
    asm("fma.rn.f32x2 %0, %1, %2, %3;" : "=l"(d) : "l"(a), "l"(b), "l"(c));
    return d;
}
__device__ __forceinline__ u64 pack2(float lo, float hi) {
    u64 r;
    asm("mov.b64 %0, {%1, %2};" : "=l"(r) : "f"(lo), "f"(hi));
    return r;
}
__device__ __forceinline__ float2 unpack2(u64 v) {
    float2 r;
    asm("mov.b64 {%0, %1}, %2;" : "=f"(r.x), "=f"(r.y) : "l"(v));
    return r;
}
__device__ __forceinline__ unsigned ld_acq(unsigned* p) {
    unsigned v;
    asm volatile("ld.acquire.gpu.u32 %0, [%1];" : "=r"(v) : "l"(p) : "memory");
    return v;
}

// ---------------- tiny init (reset barrier counter each launch) -------------
__global__ void k_init() { g_counter = 0u; }

// ---------------- embedding gather ------------------------------------------
__global__ void k_gather(const int* __restrict__ x, const float* __restrict__ tab) {
    int t = blockIdx.x;
    int row = x[t];
    float4 v = *(const float4*)(tab + (size_t)row * EE + threadIdx.x * 4);
    *(float4*)(g_emb + (size_t)t * EE + threadIdx.x * 4) = v;
}

// ---------------- bias vector: b_ih + b_hh + last_emb @ W_ih[:, E:].T --------
__global__ void k_bias(const float* __restrict__ W_ih,
                       const float* __restrict__ b_ih,
                       const float* __restrict__ b_hh) {
    int w = threadIdx.x >> 5, lane = threadIdx.x & 31;
    int g = blockIdx.x * 8 + w;
    const float* wrow = W_ih + (size_t)g * (2 * EE) + EE;
    const float* le   = g_emb + (size_t)(TT - 1) * EE;
    float s = 0.f;
#pragma unroll
    for (int i = 0; i < 4; i++) {
        float4 a = *(const float4*)(wrow + i * 128 + lane * 4);
        float4 b = *(const float4*)(le   + i * 128 + lane * 4);
        s += a.x * b.x + a.y * b.y + a.z * b.z + a.w * b.w;
    }
#pragma unroll
    for (int off = 16; off; off >>= 1) s += __shfl_xor_sync(0xffffffffu, s, off);
    if (lane == 0) g_bias4h[g] = s + b_ih[g] + b_hh[g];
}

// ---------------- SGEMM: C[M,N] = A[M,K] * B[N,K]^T + bias[n] ----------------
// 128x128 block tile, BK=16, 256 threads, 8x8 per thread, f32x2 FMAs.
__device__ __forceinline__ void sgemm_body(
    const float* __restrict__ A, int lda,
    const float* __restrict__ B, int ldb,
    const float* __restrict__ bias,
    float* __restrict__ C, int ldc,
    int M, int N, int K)
{
    __shared__ __align__(16) float As[16][128];
    __shared__ __align__(16) float Bs[16][128];
    int tid = threadIdx.x;
    int tx = tid & 15, ty = tid >> 4;
    int row0 = blockIdx.y * 128, col0 = blockIdx.x * 128;

    u64 acc[8][4];
#pragma unroll
    for (int m = 0; m < 8; m++)
#pragma unroll
        for (int n2 = 0; n2 < 4; n2++) acc[m][n2] = 0ull;

    for (int k0 = 0; k0 < K; k0 += 16) {
#pragma unroll
        for (int li = tid; li < 512; li += 256) {
            int r = li >> 2, c4 = (li & 3) << 2;
            float4 v = make_float4(0.f, 0.f, 0.f, 0.f);
            int gr = row0 + r;
            if (gr < M) v = *(const float4*)(A + (size_t)gr * lda + k0 + c4);
            As[c4][r] = v.x; As[c4 + 1][r] = v.y; As[c4 + 2][r] = v.z; As[c4 + 3][r] = v.w;
            float4 wv = make_float4(0.f, 0.f, 0.f, 0.f);
            int gn = col0 + r;
            if (gn < N) wv = *(const float4*)(B + (size_t)gn * ldb + k0 + c4);
            Bs[c4][r] = wv.x; Bs[c4 + 1][r] = wv.y; Bs[c4 + 2][r] = wv.z; Bs[c4 + 3][r] = wv.w;
        }
        __syncthreads();
#pragma unroll
        for (int k = 0; k < 16; k++) {
            float4 a0 = *(const float4*)&As[k][ty * 8];
            float4 a1 = *(const float4*)&As[k][ty * 8 + 4];
            ulonglong2 b0 = *(const ulonglong2*)&Bs[k][tx * 8];
            ulonglong2 b1 = *(const ulonglong2*)&Bs[k][tx * 8 + 4];
            float av[8] = {a0.x, a0.y, a0.z, a0.w, a1.x, a1.y, a1.z, a1.w};
            u64 bv[4] = {b0.x, b0.y, b1.x, b1.y};
#pragma unroll
            for (int m = 0; m < 8; m++) {
                u64 am = pack2(av[m], av[m]);
#pragma unroll
                for (int n2 = 0; n2 < 4; n2++)
                    acc[m][n2] = fma2(am, bv[n2], acc[m][n2]);
            }
        }
        __syncthreads();
    }
#pragma unroll
    for (int m = 0; m < 8; m++) {
        int gr = row0 + ty * 8 + m;
        if (gr >= M) continue;
#pragma unroll
        for (int n2 = 0; n2 < 4; n2++) {
            float2 s = unpack2(acc[m][n2]);
            int gc = col0 + tx * 8 + n2 * 2;
            if (gc < N)     C[(size_t)gr * ldc + gc]     = s.x + bias[gc];
            if (gc + 1 < N) C[(size_t)gr * ldc + gc + 1] = s.y + bias[gc + 1];
        }
    }
}

__global__ __launch_bounds__(256) void k_sgemm_xg(const float* __restrict__ W_ih) {
    // xg[4095,4096] = emb[0:4095] @ W_ih[:, :512]^T + bias4h
    sgemm_body(g_emb, EE, W_ih, 2 * EE, g_bias4h, g_xg, G4, TM1, G4, EE);
}

__global__ __launch_bounds__(256) void k_sgemm_out(const float* __restrict__ W_out,
                                                   const float* __restrict__ b_out,
                                                   float* __restrict__ out) {
    // out[4095,1221] = hs @ W_out^T + b_out
    sgemm_body(g_hs, HH, W_out, HH, b_out, out, CC, TM1, CC, HH);
}

// ---------------- persistent LSTM recurrence --------------------------------
// 128 CTAs x 256 threads. CTA b owns j = b*8 + warp, warp computes the 4 gate
// dots for its j with W_hh rows held in registers (128 regs/lane).
__global__ __launch_bounds__(256, 1) void k_lstm(const float* __restrict__ W_hh) {
    __shared__ __align__(16) float h_s[HH];
    int tid = threadIdx.x;
    int w = tid >> 5, lane = tid & 31;
    int j = blockIdx.x * 8 + w;

    // Load this warp's W_hh rows into registers: 4 gates x 32 k per lane,
    // k = i*128 + lane*4 + {0..3}, as 8 ulonglong2 (f32x2 pairs) per gate.
    ulonglong2 wr[4][8];
#pragma unroll
    for (int g = 0; g < 4; g++) {
        const float* base = W_hh + (size_t)(g * HH + j) * HH + lane * 4;
#pragma unroll
        for (int i = 0; i < 8; i++)
            wr[g][i] = *(const ulonglong2*)(base + i * 128);
    }

    float c = 0.f;
    float xgv = 0.f;
    if (lane < 4) xgv = g_xg[(size_t)lane * HH + j];   // t = 0 prefetch

    for (int t = 0; t < TM1; t++) {
        // stage h_{t-1} into smem (zeros for t==0)
        float4 hv = make_float4(0.f, 0.f, 0.f, 0.f);
        if (t > 0) hv = *(const float4*)(g_hs + (size_t)(t - 1) * HH + tid * 4);
        *(float4*)&h_s[tid * 4] = hv;
        __syncthreads();

        // 4 gate dot products over K=1024, f32x2 FMAs
        u64 acc[4] = {0ull, 0ull, 0ull, 0ull};
#pragma unroll
        for (int i = 0; i < 8; i++) {
            ulonglong2 h2 = *(const ulonglong2*)&h_s[i * 128 + lane * 4];
#pragma unroll
            for (int g = 0; g < 4; g++) {
                acc[g] = fma2(wr[g][i].x, h2.x, acc[g]);
                acc[g] = fma2(wr[g][i].y, h2.y, acc[g]);
            }
        }
        float r0, r1, r2, r3;
        { float2 s = unpack2(acc[0]); r0 = s.x + s.y; }
        { float2 s = unpack2(acc[1]); r1 = s.x + s.y; }
        { float2 s = unpack2(acc[2]); r2 = s.x + s.y; }
        { float2 s = unpack2(acc[3]); r3 = s.x + s.y; }
#pragma unroll
        for (int off = 16; off; off >>= 1) {
            r0 += __shfl_xor_sync(0xffffffffu, r0, off);
            r1 += __shfl_xor_sync(0xffffffffu, r1, off);
            r2 += __shfl_xor_sync(0xffffffffu, r2, off);
            r3 += __shfl_xor_sync(0xffffffffu, r3, off);
        }

        // Activations: lanes 0..3 handle gates i,f,g,o. tanh(x)=2*sigmoid(2x)-1
        float rv = (lane == 0) ? r0 : (lane == 1) ? r1 : (lane == 2) ? r2 : r3;
        float s  = rv + xgv;
        float si = (lane == 2) ? (s + s) : s;
        float a  = __fdividef(1.f, 1.f + __expf(-si));
        if (lane == 2) a = 2.f * a - 1.f;
        float gi = __shfl_sync(0xffffffffu, a, 0);
        float gf = __shfl_sync(0xffffffffu, a, 1);
        float gg = __shfl_sync(0xffffffffu, a, 2);
        float go = __shfl_sync(0xffffffffu, a, 3);
        if (lane == 0) {
            c = gf * c + gi * gg;
            float tc = __fdividef(2.f, 1.f + __expf(-2.f * c)) - 1.f;
            g_hs[(size_t)t * HH + j] = go * tc;
        }

        // prefetch next step's xg during the barrier wait
        int tn = (t + 1 < TM1) ? (t + 1) : t;
        if (lane < 4) xgv = g_xg[(size_t)tn * G4 + lane * HH + j];

        // grid barrier: monotonic counter, fence + atomic arrive, acquire spin
        __syncthreads();
        if (tid == 0) {
            __threadfence();
            atomicAdd(&g_counter, 1u);
            unsigned target = (unsigned)(t + 1) * NCTA;
            while (ld_acq(&g_counter) < target) { }
        }
        __syncthreads();
    }
}

// ---------------- launch ------------------------------------------------------
extern "C" void kernel_launch(void* const* d_in, const int* in_sizes, int n_in,
                              void* d_out, int out_size) {
    const int*   x     = (const int*)d_in[0];
    const float* table = (const float*)d_in[1];
    const float* W_ih  = (const float*)d_in[2];
    const float* W_hh  = (const float*)d_in[3];
    const float* b_ih  = (const float*)d_in[4];
    const float* b_hh  = (const float*)d_in[5];
    const float* W_out = (const float*)d_in[6];
    const float* b_out = (const float*)d_in[7];
    float* out = (float*)d_out;
    (void)in_sizes; (void)n_in; (void)out_size;

    k_init<<<1, 1>>>();
    k_gather<<<TT, 128>>>(x, table);
    k_bias<<<G4 / 8, 256>>>(W_ih, b_ih, b_hh);
    {   // x_gates GEMM: M=4095, N=4096, K=512
        dim3 grid((G4 + 127) / 128, (TM1 + 127) / 128);
        k_sgemm_xg<<<grid, 256>>>(W_ih);
    }
    k_lstm<<<NCTA, 256>>>(W_hh);
    {   // output GEMM: M=4095, N=1221, K=1024
        dim3 grid((CC + 127) / 128, (TM1 + 127) / 128);
        k_sgemm_out<<<grid, 256>>>(W_out, b_out, out);
    }
}

// round 2
// speedup vs baseline: 1.0305x; 1.0305x over previous
#include <cuda_runtime.h>

// Problem constants
#define TT   4096      // sequence length T
#define TM1  4095      // T-1 steps
#define EE   512       // embedding dim E
#define HH   1024      // hidden dim H
#define G4   4096      // 4*H
#define CC   1221      // output classes C
#define NCTA 128       // persistent CTAs for the recurrence

typedef unsigned long long u64;

#define CANARY 0x7fc0deadu   // qNaN payload: h = o*tanh(c) in (-1,1) can never equal it

// ---------------- scratch (static device globals; no allocation allowed) ----
__device__ float    g_emb[(size_t)TT * EE];        // gathered embeddings  (8 MB)
__device__ float    g_bias4h[G4];                  // b_ih + b_hh + last@W_ih[:,E:]
__device__ float    g_xg[(size_t)TM1 * G4];        // precomputed input gates (67 MB)
__device__ float    g_hs[(size_t)TM1 * HH];        // all hidden states (16.8 MB)

// ---------------- helpers ---------------------------------------------------
__device__ __forceinline__ u64 fma2(u64 a, u64 b, u64 c) {
    u64 d;
    asm("fma.rn.f32x2 %0, %1, %2, %3;" : "=l"(d) : "l"(a), "l"(b), "l"(c));
    return d;
}
__device__ __forceinline__ u64 pack2(float lo, float hi) {
    u64 r;
    asm("mov.b64 %0, {%1, %2};" : "=l"(r) : "f"(lo), "f"(hi));
    return r;
}
__device__ __forceinline__ float2 unpack2(u64 v) {
    float2 r;
    asm("mov.b64 {%0, %1}, %2;" : "=f"(r.x), "=f"(r.y) : "l"(v));
    return r;
}
__device__ __forceinline__ uint4 ld_vol4(const void* p) {
    uint4 v;
    asm volatile("ld.volatile.global.v4.u32 {%0,%1,%2,%3}, [%4];"
                 : "=r"(v.x), "=r"(v.y), "=r"(v.z), "=r"(v.w)
                 : "l"(p) : "memory");
    return v;
}
__device__ __forceinline__ void st_vol_f32(float* p, float x) {
    asm volatile("st.volatile.global.f32 [%0], %1;" :: "l"(p), "f"(x) : "memory");
}

// ---------------- canary fill of g_hs (every launch) -------------------------
__global__ void k_canary() {
    size_t i = ((size_t)blockIdx.x * 256 + threadIdx.x) * 4;   // 4095*256*4 = TM1*HH
    uint4 c4 = make_uint4(CANARY, CANARY, CANARY, CANARY);
    *(uint4*)((unsigned*)g_hs + i) = c4;
}

// ---------------- embedding gather ------------------------------------------
__global__ void k_gather(const int* __restrict__ x, const float* __restrict__ tab) {
    int t = blockIdx.x;
    int row = x[t];
    float4 v = *(const float4*)(tab + (size_t)row * EE + threadIdx.x * 4);
    *(float4*)(g_emb + (size_t)t * EE + threadIdx.x * 4) = v;
}

// ---------------- bias vector: b_ih + b_hh + last_emb @ W_ih[:, E:].T --------
__global__ void k_bias(const float* __restrict__ W_ih,
                       const float* __restrict__ b_ih,
                       const float* __restrict__ b_hh) {
    int w = threadIdx.x >> 5, lane = threadIdx.x & 31;
    int g = blockIdx.x * 8 + w;
    const float* wrow = W_ih + (size_t)g * (2 * EE) + EE;
    const float* le   = g_emb + (size_t)(TT - 1) * EE;
    float s = 0.f;
#pragma unroll
    for (int i = 0; i < 4; i++) {
        float4 a = *(const float4*)(wrow + i * 128 + lane * 4);
        float4 b = *(const float4*)(le   + i * 128 + lane * 4);
        s += a.x * b.x + a.y * b.y + a.z * b.z + a.w * b.w;
    }
#pragma unroll
    for (int off = 16; off; off >>= 1) s += __shfl_xor_sync(0xffffffffu, s, off);
    if (lane == 0) g_bias4h[g] = s + b_ih[g] + b_hh[g];
}

// ---------------- SGEMM: C[M,N] = A[M,K] * B[N,K]^T + bias[n] ----------------
__device__ __forceinline__ void sgemm_body(
    const float* __restrict__ A, int lda,
    const float* __restrict__ B, int ldb,
    const float* __restrict__ bias,
    float* __restrict__ C, int ldc,
    int M, int N, int K)
{
    __shared__ __align__(16) float As[16][128];
    __shared__ __align__(16) float Bs[16][128];
    int tid = threadIdx.x;
    int tx = tid & 15, ty = tid >> 4;
    int row0 = blockIdx.y * 128, col0 = blockIdx.x * 128;

    u64 acc[8][4];
#pragma unroll
    for (int m = 0; m < 8; m++)
#pragma unroll
        for (int n2 = 0; n2 < 4; n2++) acc[m][n2] = 0ull;

    for (int k0 = 0; k0 < K; k0 += 16) {
#pragma unroll
        for (int li = tid; li < 512; li += 256) {
            int r = li >> 2, c4 = (li & 3) << 2;
            float4 v = make_float4(0.f, 0.f, 0.f, 0.f);
            int gr = row0 + r;
            if (gr < M) v = *(const float4*)(A + (size_t)gr * lda + k0 + c4);
            As[c4][r] = v.x; As[c4 + 1][r] = v.y; As[c4 + 2][r] = v.z; As[c4 + 3][r] = v.w;
            float4 wv = make_float4(0.f, 0.f, 0.f, 0.f);
            int gn = col0 + r;
            if (gn < N) wv = *(const float4*)(B + (size_t)gn * ldb + k0 + c4);
            Bs[c4][r] = wv.x; Bs[c4 + 1][r] = wv.y; Bs[c4 + 2][r] = wv.z; Bs[c4 + 3][r] = wv.w;
        }
        __syncthreads();
#pragma unroll
        for (int k = 0; k < 16; k++) {
            float4 a0 = *(const float4*)&As[k][ty * 8];
            float4 a1 = *(const float4*)&As[k][ty * 8 + 4];
            ulonglong2 b0 = *(const ulonglong2*)&Bs[k][tx * 8];
            ulonglong2 b1 = *(const ulonglong2*)&Bs[k][tx * 8 + 4];
            float av[8] = {a0.x, a0.y, a0.z, a0.w, a1.x, a1.y, a1.z, a1.w};
            u64 bv[4] = {b0.x, b0.y, b1.x, b1.y};
#pragma unroll
            for (int m = 0; m < 8; m++) {
                u64 am = pack2(av[m], av[m]);
#pragma unroll
                for (int n2 = 0; n2 < 4; n2++)
                    acc[m][n2] = fma2(am, bv[n2], acc[m][n2]);
            }
        }
        __syncthreads();
    }
#pragma unroll
    for (int m = 0; m < 8; m++) {
        int gr = row0 + ty * 8 + m;
        if (gr >= M) continue;
#pragma unroll
        for (int n2 = 0; n2 < 4; n2++) {
            float2 s = unpack2(acc[m][n2]);
            int gc = col0 + tx * 8 + n2 * 2;
            if (gc < N)     C[(size_t)gr * ldc + gc]     = s.x + bias[gc];
            if (gc + 1 < N) C[(size_t)gr * ldc + gc + 1] = s.y + bias[gc + 1];
        }
    }
}

__global__ __launch_bounds__(256) void k_sgemm_xg(const float* __restrict__ W_ih) {
    sgemm_body(g_emb, EE, W_ih, 2 * EE, g_bias4h, g_xg, G4, TM1, G4, EE);
}

__global__ __launch_bounds__(256) void k_sgemm_out(const float* __restrict__ W_out,
                                                   const float* __restrict__ b_out,
                                                   float* __restrict__ out) {
    sgemm_body(g_hs, HH, W_out, HH, b_out, out, CC, TM1, CC, HH);
}

// ---------------- persistent LSTM recurrence (barrier-free dataflow) ---------
// 128 CTAs x 256 threads. CTA b owns j = b*8 + warp. W_hh rows in registers.
// No grid barrier: h_{t-1} chunks are polled directly out of g_hs; the NaN
// canary (pre-filled) marks not-yet-written values. The data is the flag.
__global__ __launch_bounds__(256, 1) void k_lstm(const float* __restrict__ W_hh) {
    __shared__ __align__(16) float h_s[HH];
    int tid = threadIdx.x;
    int w = tid >> 5, lane = tid & 31;
    int j = blockIdx.x * 8 + w;

    // This warp's W_hh rows in registers: 4 gates x 32 k per lane (f32x2 pairs)
    ulonglong2 wr[4][8];
#pragma unroll
    for (int g = 0; g < 4; g++) {
        const float* base = W_hh + (size_t)(g * HH + j) * HH + lane * 4;
#pragma unroll
        for (int i = 0; i < 8; i++)
            wr[g][i] = *(const ulonglong2*)(base + i * 128);
    }

    float c = 0.f;
    float xgv = 0.f;
    if (lane < 4) xgv = g_xg[(size_t)lane * HH + j];   // t = 0 prefetch

    for (int t = 0; t < TM1; t++) {
        // stage h_{t-1}: poll own 16B chunk until all 4 floats are non-canary
        if (t == 0) {
            *(float4*)&h_s[tid * 4] = make_float4(0.f, 0.f, 0.f, 0.f);
        } else {
            const void* src = g_hs + (size_t)(t - 1) * HH + tid * 4;
            uint4 v;
            do {
                v = ld_vol4(src);
            } while (v.x == CANARY || v.y == CANARY || v.z == CANARY || v.w == CANARY);
            *(uint4*)&h_s[tid * 4] = v;
        }
        __syncthreads();

        // 4 gate dot products over K=1024, f32x2 FMAs
        u64 acc[4] = {0ull, 0ull, 0ull, 0ull};
#pragma unroll
        for (int i = 0; i < 8; i++) {
            ulonglong2 h2 = *(const ulonglong2*)&h_s[i * 128 + lane * 4];
#pragma unroll
            for (int g = 0; g < 4; g++) {
                acc[g] = fma2(wr[g][i].x, h2.x, acc[g]);
                acc[g] = fma2(wr[g][i].y, h2.y, acc[g]);
            }
        }
        float r0, r1, r2, r3;
        { float2 s = unpack2(acc[0]); r0 = s.x + s.y; }
        { float2 s = unpack2(acc[1]); r1 = s.x + s.y; }
        { float2 s = unpack2(acc[2]); r2 = s.x + s.y; }
        { float2 s = unpack2(acc[3]); r3 = s.x + s.y; }
#pragma unroll
        for (int off = 16; off; off >>= 1) {
            r0 += __shfl_xor_sync(0xffffffffu, r0, off);
            r1 += __shfl_xor_sync(0xffffffffu, r1, off);
            r2 += __shfl_xor_sync(0xffffffffu, r2, off);
            r3 += __shfl_xor_sync(0xffffffffu, r3, off);
        }

        // Activations: lanes 0..3 handle gates i,f,g,o. tanh(x)=2*sigmoid(2x)-1
        float rv = (lane == 0) ? r0 : (lane == 1) ? r1 : (lane == 2) ? r2 : r3;
        float s  = rv + xgv;
        float si = (lane == 2) ? (s + s) : s;
        float a  = __fdividef(1.f, 1.f + __expf(-si));
        if (lane == 2) a = 2.f * a - 1.f;
        float gi = __shfl_sync(0xffffffffu, a, 0);
        float gf = __shfl_sync(0xffffffffu, a, 1);
        float gg = __shfl_sync(0xffffffffu, a, 2);
        float go = __shfl_sync(0xffffffffu, a, 3);
        if (lane == 0) {
            c = gf * c + gi * gg;
            float tc = __fdividef(2.f, 1.f + __expf(-2.f * c)) - 1.f;
            st_vol_f32(g_hs + (size_t)t * HH + j, go * tc);   // publish h_t[j]
        }

        // prefetch next step's xg (input side is precomputed, no hazard)
        int tn = (t + 1 < TM1) ? (t + 1) : t;
        if (lane < 4) xgv = g_xg[(size_t)tn * G4 + lane * HH + j];

        // protect h_s against early overwrite by fast threads in next iteration
        __syncthreads();
    }
}

// ---------------- launch ------------------------------------------------------
extern "C" void kernel_launch(void* const* d_in, const int* in_sizes, int n_in,
                              void* d_out, int out_size) {
    const int*   x     = (const int*)d_in[0];
    const float* table = (const float*)d_in[1];
    const float* W_ih  = (const float*)d_in[2];
    const float* W_hh  = (const float*)d_in[3];
    const float* b_ih  = (const float*)d_in[4];
    const float* b_hh  = (const float*)d_in[5];
    const float* W_out = (const float*)d_in[6];
    const float* b_out = (const float*)d_in[7];
    float* out = (float*)d_out;
    (void)in_sizes; (void)n_in; (void)out_size;

    k_canary<<<TM1, 256>>>();              // reset dataflow canaries (every launch)
    k_gather<<<TT, 128>>>(x, table);
    k_bias<<<G4 / 8, 256>>>(W_ih, b_ih, b_hh);
    {   // x_gates GEMM: M=4095, N=4096, K=512
        dim3 grid((G4 + 127) / 128, (TM1 + 127) / 128);
        k_sgemm_xg<<<grid, 256>>>(W_ih);
    }
    k_lstm<<<NCTA, 256>>>(W_hh);
    {   // output GEMM: M=4095, N=1221, K=1024
        dim3 grid((CC + 127) / 128, (TM1 + 127) / 128);
        k_sgemm_out<<<grid, 256>>>(W_out, b_out, out);
    }
}